// round 1
// baseline (speedup 1.0000x reference)
#include <cuda_runtime.h>
#include <math.h>

#define BB 8
#define TT 2048
#define CC 512
#define NNODE 1024

static const int BM = 128, BN = 128, BK = 8, TM = 8, TN = 8;

// ---------------- device scratch (static: no allocations allowed) ----------------
__device__ float g_k[BB * TT * CC];          // 33.5 MB
__device__ float g_v[BB * TT * CC];          // 33.5 MB
__device__ float g_q[BB * NNODE * CC];       // 16.8 MB
__device__ float g_outpre[BB * NNODE * CC];  // 16.8 MB
__device__ unsigned long long g_colmax[BB * TT];  // packed (float key, node idx) per token
__device__ unsigned int g_Mkey[BB * NNODE];       // per-node max (orderable-uint encoded)
__device__ float g_Z[BB * NNODE];                 // per-node softmax denominator

// Monotone float <-> uint mapping so atomicMax on uint == max on float
__device__ __forceinline__ unsigned int fkey(float f) {
    unsigned int u = __float_as_uint(f);
    return (u & 0x80000000u) ? ~u : (u | 0x80000000u);
}
__device__ __forceinline__ float funkey(unsigned int u) {
    unsigned int v = (u & 0x80000000u) ? (u & 0x7fffffffu) : ~u;
    return __uint_as_float(v);
}

// ---------------- generic fp32 GEMM, 128x128x8 tile, 8x8 microtile, double-buffered ----------------
// C[m,n] = sum_k A[m,k] * B'[k,n]   where B' = Bm[n,k] if BTRANS else Bm[k,n]
// BIAS_ROW: += bias[m]; BIAS_COL: += bias[n]
// SIM_EPI: no C store; per-column (n) max over rows (m) of scale*acc, atomicMax into colmax.
template <bool BTRANS, bool BIAS_ROW, bool BIAS_COL, bool SIM_EPI>
__global__ __launch_bounds__(256, 2) void gemm_k(
    const float* __restrict__ A, const float* __restrict__ Bm,
    const float* __restrict__ bias, float* __restrict__ Cout,
    int M, int Nd, int K,
    long sAz, long sBz, long sCz,
    float scale, unsigned long long* colmax, long sMz)
{
    __shared__ float As[2][BK][BM];
    __shared__ float Bs[2][BK][BN];

    const int z = blockIdx.z;
    A += (long)z * sAz;
    Bm += (long)z * sBz;

    const int tid = threadIdx.x;
    const int m0 = blockIdx.y * BM;
    const int n0 = blockIdx.x * BN;

    const int aRow = tid >> 1;
    const int aCol = (tid & 1) * 4;
    const int bRow = BTRANS ? (tid >> 1) : (tid >> 5);
    const int bCol = BTRANS ? (tid & 1) * 4 : (tid & 31) * 4;

    const int tRow = (tid >> 4) * TM;
    const int tCol = (tid & 15) * TN;

    const float* Aptr = A + (long)(m0 + aRow) * K + aCol;
    const float* Bptr = BTRANS ? (Bm + (long)(n0 + bRow) * K + bCol)
                               : (Bm + (long)bRow * Nd + n0 + bCol);

    float acc[TM][TN];
#pragma unroll
    for (int i = 0; i < TM; i++)
#pragma unroll
        for (int j = 0; j < TN; j++) acc[i][j] = 0.f;

    const int nT = K / BK;

    float4 a4 = *reinterpret_cast<const float4*>(Aptr);
    float4 b4 = *reinterpret_cast<const float4*>(Bptr);
    As[0][aCol + 0][aRow] = a4.x; As[0][aCol + 1][aRow] = a4.y;
    As[0][aCol + 2][aRow] = a4.z; As[0][aCol + 3][aRow] = a4.w;
    if (BTRANS) {
        Bs[0][bCol + 0][bRow] = b4.x; Bs[0][bCol + 1][bRow] = b4.y;
        Bs[0][bCol + 2][bRow] = b4.z; Bs[0][bCol + 3][bRow] = b4.w;
    } else {
        *reinterpret_cast<float4*>(&Bs[0][bRow][bCol]) = b4;
    }
    __syncthreads();

    int cur = 0;
    for (int kt = 0; kt < nT; ++kt) {
        if (kt + 1 < nT) {
            a4 = *reinterpret_cast<const float4*>(Aptr + (long)(kt + 1) * BK);
            b4 = *reinterpret_cast<const float4*>(
                Bptr + (BTRANS ? (long)(kt + 1) * BK : (long)(kt + 1) * BK * Nd));
        }
        float rA[TM], rB[TN];
#pragma unroll
        for (int d = 0; d < BK; ++d) {
#pragma unroll
            for (int i = 0; i < TM; i++) rA[i] = As[cur][d][tRow + i];
#pragma unroll
            for (int j = 0; j < TN; j++) rB[j] = Bs[cur][d][tCol + j];
#pragma unroll
            for (int i = 0; i < TM; i++)
#pragma unroll
                for (int j = 0; j < TN; j++)
                    acc[i][j] = fmaf(rA[i], rB[j], acc[i][j]);
        }
        if (kt + 1 < nT) {
            int nx = cur ^ 1;
            As[nx][aCol + 0][aRow] = a4.x; As[nx][aCol + 1][aRow] = a4.y;
            As[nx][aCol + 2][aRow] = a4.z; As[nx][aCol + 3][aRow] = a4.w;
            if (BTRANS) {
                Bs[nx][bCol + 0][bRow] = b4.x; Bs[nx][bCol + 1][bRow] = b4.y;
                Bs[nx][bCol + 2][bRow] = b4.z; Bs[nx][bCol + 3][bRow] = b4.w;
            } else {
                *reinterpret_cast<float4*>(&Bs[nx][bRow][bCol]) = b4;
            }
        }
        __syncthreads();
        cur ^= 1;
    }

    if constexpr (!SIM_EPI) {
        float* Cz = Cout + (long)z * sCz;
#pragma unroll
        for (int i = 0; i < TM; i++) {
            const long row = m0 + tRow + i;
            float rb = 0.f;
            if constexpr (BIAS_ROW) rb = bias[row];
#pragma unroll
            for (int j = 0; j < TN; j += 4) {
                float4 o;
                o.x = acc[i][j + 0] + rb;
                o.y = acc[i][j + 1] + rb;
                o.z = acc[i][j + 2] + rb;
                o.w = acc[i][j + 3] + rb;
                if constexpr (BIAS_COL) {
                    o.x += bias[n0 + tCol + j + 0];
                    o.y += bias[n0 + tCol + j + 1];
                    o.z += bias[n0 + tCol + j + 2];
                    o.w += bias[n0 + tCol + j + 3];
                }
                *reinterpret_cast<float4*>(&Cz[row * Nd + n0 + tCol + j]) = o;
            }
        }
    } else {
        // per-column argmax over the 128 rows of this block, then atomic merge
        __shared__ unsigned long long red[16][BN];
#pragma unroll
        for (int j = 0; j < TN; j++) {
            float bv = acc[0][j] * scale;
            int bi = m0 + tRow;
#pragma unroll
            for (int i = 1; i < TM; i++) {
                float v = acc[i][j] * scale;
                if (v > bv) { bv = v; bi = m0 + tRow + i; }
            }
            red[tid >> 4][tCol + j] =
                ((unsigned long long)fkey(bv) << 32) | (unsigned int)bi;
        }
        __syncthreads();
        if (tid < BN) {
            unsigned long long mx = red[0][tid];
#pragma unroll
            for (int r = 1; r < 16; r++) {
                unsigned long long t = red[r][tid];
                mx = (t > mx) ? t : mx;
            }
            atomicMax(&colmax[z * sMz + n0 + tid], mx);
        }
    }
}

// ---------------- small kernels ----------------
__global__ void init_kernel() {
    int i = blockIdx.x * blockDim.x + threadIdx.x;
    int stride = gridDim.x * blockDim.x;
    for (int j = i; j < BB * TT; j += stride) g_colmax[j] = 0ull;
    for (int j = i; j < BB * NNODE; j += stride) { g_Mkey[j] = 0u; g_Z[j] = 0.f; }
    for (int j = i; j < BB * NNODE * CC; j += stride) g_outpre[j] = 0.f;
}

__global__ void node_max_kernel() {
    int i = blockIdx.x * blockDim.x + threadIdx.x;
    if (i >= BB * TT) return;
    int b = i / TT;
    unsigned long long p = g_colmax[i];
    unsigned int n = (unsigned int)(p & 0xffffffffu);
    atomicMax(&g_Mkey[b * NNODE + n], (unsigned int)(p >> 32));
}

__global__ void node_sum_kernel() {
    int i = blockIdx.x * blockDim.x + threadIdx.x;
    if (i >= BB * TT) return;
    int b = i / TT;
    unsigned long long p = g_colmax[i];
    unsigned int n = (unsigned int)(p & 0xffffffffu);
    int bn = b * NNODE + n;
    float m = funkey((unsigned int)(p >> 32));
    atomicAdd(&g_Z[bn], expf(m - funkey(g_Mkey[bn])));
}

__global__ void att_scatter_kernel(float* __restrict__ att) {
    int i = blockIdx.x * blockDim.x + threadIdx.x;
    if (i >= BB * TT) return;
    int b = i / TT;
    int t = i % TT;
    unsigned long long p = g_colmax[i];
    unsigned int n = (unsigned int)(p & 0xffffffffu);
    int bn = b * NNODE + n;
    float m = funkey((unsigned int)(p >> 32));
    float w = expf(m - funkey(g_Mkey[bn])) / g_Z[bn];
    att[(long)bn * TT + t] = w;
}

__global__ void outpre_scatter_kernel() {
    int i = blockIdx.x;  // one block per (b,t)
    int b = i / TT;
    unsigned long long p = g_colmax[i];
    unsigned int n = (unsigned int)(p & 0xffffffffu);
    int bn = b * NNODE + n;
    float m = funkey((unsigned int)(p >> 32));
    float w = expf(m - funkey(g_Mkey[bn])) / g_Z[bn];
    const float* vrow = g_v + (long)i * CC;
    float* orow = g_outpre + (long)bn * CC;
    for (int c = threadIdx.x; c < CC; c += blockDim.x)
        atomicAdd(&orow[c], w * vrow[c]);
}

// ---------------- launch ----------------
extern "C" void kernel_launch(void* const* d_in, const int* in_sizes, int n_in,
                              void* d_out, int out_size)
{
    const float* x    = (const float*)d_in[0];
    const float* Wq   = (const float*)d_in[1];
    const float* bq   = (const float*)d_in[2];
    const float* Wk   = (const float*)d_in[3];
    const float* Wv   = (const float*)d_in[4];
    const float* Wout = (const float*)d_in[5];
    const float* bout = (const float*)d_in[6];

    float* out = (float*)d_out;                       // [B, N, C]
    float* att = out + (long)BB * NNODE * CC;         // [B, N, T]

    float* kp; cudaGetSymbolAddress((void**)&kp, g_k);
    float* vp; cudaGetSymbolAddress((void**)&vp, g_v);
    float* qp; cudaGetSymbolAddress((void**)&qp, g_q);
    float* op; cudaGetSymbolAddress((void**)&op, g_outpre);
    unsigned long long* cm; cudaGetSymbolAddress((void**)&cm, g_colmax);

    const float scale = 1.0f / sqrtf((float)CC);

    init_kernel<<<2048, 256>>>();
    cudaMemsetAsync(att, 0, (size_t)BB * NNODE * TT * sizeof(float), 0);

    // k = x @ Wk^T, v = x @ Wv^T   (M = B*T, N = C, K = C)
    {
        dim3 g(CC / BN, (BB * TT) / BM, 1);
        gemm_k<true, false, false, false><<<g, 256>>>(
            x, Wk, nullptr, kp, BB * TT, CC, CC, 0, 0, 0, 0.f, nullptr, 0);
        gemm_k<true, false, false, false><<<g, 256>>>(
            x, Wv, nullptr, vp, BB * TT, CC, CC, 0, 0, 0, 0.f, nullptr, 0);
    }
    // q[b] = Wq @ x[b] + bq   (M = N_node, N = C, K = T), NN GEMM
    {
        dim3 g(CC / BN, NNODE / BM, BB);
        gemm_k<false, true, false, false><<<g, 256>>>(
            Wq, x, bq, qp, NNODE, CC, TT,
            0, (long)TT * CC, (long)NNODE * CC, 0.f, nullptr, 0);
    }
    // sim[b] = scale * q[b] @ k[b]^T, fused column-argmax epilogue (no store)
    {
        dim3 g(TT / BN, NNODE / BM, BB);
        gemm_k<true, false, false, true><<<g, 256>>>(
            qp, kp, nullptr, nullptr, NNODE, TT, CC,
            (long)NNODE * CC, (long)TT * CC, 0, scale, cm, (long)TT);
    }
    node_max_kernel<<<(BB * TT) / 256, 256>>>();
    node_sum_kernel<<<(BB * TT) / 256, 256>>>();
    att_scatter_kernel<<<(BB * TT) / 256, 256>>>(att);
    outpre_scatter_kernel<<<BB * TT, 128>>>();
    // out = out_pre @ Wout^T + bout  (M = B*N_node, N = C, K = C)
    {
        dim3 g(CC / BN, (BB * NNODE) / BM, 1);
        gemm_k<true, false, true, false><<<g, 256>>>(
            op, Wout, bout, out, BB * NNODE, CC, CC, 0, 0, 0, 0.f, nullptr, 0);
    }
}

// round 4
// speedup vs baseline: 1.1943x; 1.1943x over previous
#include <cuda_runtime.h>
#include <math.h>
#include <stdint.h>

#define BB 8
#define TT 2048
#define CC 512
#define NNODE 1024

// ============================ scratch (static) ============================
#define AL __align__(128)
__device__ AL float g_xh[BB * TT * CC];
__device__ AL float g_xl[BB * TT * CC];
__device__ AL float g_xTh[BB * CC * TT];
__device__ AL float g_xTl[BB * CC * TT];
__device__ AL float g_Wqh[NNODE * TT];
__device__ AL float g_Wql[NNODE * TT];
__device__ AL float g_Wkh[CC * CC];
__device__ AL float g_Wkl[CC * CC];
__device__ AL float g_Wvh[CC * CC];
__device__ AL float g_Wvl[CC * CC];
__device__ AL float g_Woh[CC * CC];
__device__ AL float g_Wol[CC * CC];
__device__ AL float g_kh[BB * TT * CC];
__device__ AL float g_kl[BB * TT * CC];
__device__ AL float g_v[BB * TT * CC];
__device__ AL float g_qh[BB * NNODE * CC];
__device__ AL float g_ql[BB * NNODE * CC];
__device__ AL float g_op[BB * NNODE * CC];
__device__ AL float g_oph[BB * NNODE * CC];
__device__ AL float g_opl[BB * NNODE * CC];
__device__ AL unsigned long long g_colmax[BB * TT];
__device__ AL unsigned int g_Mkey[BB * NNODE];
__device__ AL float g_Z[BB * NNODE];

// ============================ helpers ============================
__device__ __forceinline__ unsigned int fkey(float f) {
    unsigned int u = __float_as_uint(f);
    return (u & 0x80000000u) ? ~u : (u | 0x80000000u);
}
__device__ __forceinline__ float funkey(unsigned int u) {
    unsigned int v = (u & 0x80000000u) ? (u & 0x7fffffffu) : ~u;
    return __uint_as_float(v);
}
__device__ __forceinline__ float tf32_round(float x) {
    unsigned int r;
    asm("cvt.rna.tf32.f32 %0, %1;" : "=r"(r) : "f"(x));
    return __uint_as_float(r);
}
__device__ __forceinline__ uint32_t smem_u32(const void* p) {
    uint32_t a;
    asm("{ .reg .u64 t; cvta.to.shared.u64 t, %1; cvt.u32.u64 %0, t; }" : "=r"(a) : "l"(p));
    return a;
}
__device__ __forceinline__ void cp16(uint32_t dst, const void* src) {
    asm volatile("cp.async.cg.shared.global [%0], [%1], 16;" :: "r"(dst), "l"(src) : "memory");
}
__device__ __forceinline__ void cp_commit() {
    asm volatile("cp.async.commit_group;" ::: "memory");
}
template <int N> __device__ __forceinline__ void cp_wait() {
    asm volatile("cp.async.wait_group %0;" :: "n"(N) : "memory");
}
// m16n8k8 tf32 mma (portable ISA, sm_80+)
__device__ __forceinline__ void mma8(float& d0, float& d1, float& d2, float& d3,
                                     unsigned a0, unsigned a1, unsigned a2, unsigned a3,
                                     unsigned b0, unsigned b1) {
    asm volatile(
        "mma.sync.aligned.m16n8k8.row.col.f32.tf32.tf32.f32 "
        "{%0,%1,%2,%3},{%4,%5,%6,%7},{%8,%9},{%0,%1,%2,%3};"
        : "+f"(d0), "+f"(d1), "+f"(d2), "+f"(d3)
        : "r"(a0), "r"(a1), "r"(a2), "r"(a3), "r"(b0), "r"(b1));
}

// ============================ mma.sync tf32 3-split NT GEMM ============================
// C[m,n] = sum_k (Ah+Al)[m,k] * (Bh+Bl)[n,k]     (lo*lo dropped)
// Block 128x128, BK=16, 8 warps as 2(m) x 4(n), warp tile 64x32.
// EPI: 0 plain, 1 plain+colbias, 2 hilo, 3 hilo+rowbias, 4 argmax->colmax
static const int SROW = 20;                 // smem row stride in floats (conflict-free, 16B-aligned)
static const int TILE_BYTES = 128 * SROW * 4;      // 10240
static const int STAGE_BYTES = 4 * TILE_BYTES;     // 40960
static const int RED_OFF = 2 * STAGE_BYTES;        // 81920
static const int SMEM_SZ = RED_OFF + 128 * 8;      // 82944

template <int EPI>
__global__ __launch_bounds__(256, 2) void gemm_mma(
    const float* __restrict__ Ah, const float* __restrict__ Al,
    const float* __restrict__ Bh, const float* __restrict__ Bl,
    const float* __restrict__ bias,
    float* __restrict__ C0, float* __restrict__ C1,
    int Nd, int K,
    long sAz, long sBz, long sCz,
    float scale, unsigned long long* colmax, long sMz)
{
    extern __shared__ __align__(16) char smem[];
    const uint32_t sb = smem_u32(smem);
    const int tid = threadIdx.x;
    const int lane = tid & 31;
    const int wid = tid >> 5;
    const int wm = wid >> 2;            // 0..1
    const int wn = wid & 3;             // 0..3
    const int grp = lane >> 2;          // 0..7
    const int qd = lane & 3;            // 0..3
    const int z = blockIdx.z;
    const long m0 = (long)blockIdx.y * 128;
    const long n0 = (long)blockIdx.x * 128;

    // ---- gmem -> smem loader slots: 8 x 16B chunks per thread per stage ----
    const float* pT[4] = { Ah + z * sAz + m0 * K, Al + z * sAz + m0 * K,
                           Bh + z * sBz + n0 * K, Bl + z * sBz + n0 * K };
    const float* src[8];
    uint32_t dst[8];
#pragma unroll
    for (int i = 0; i < 8; i++) {
        int w = i * 256 + tid;          // 0..2047
        int tile = w >> 9;              // 512 chunks per tile
        int row = (w >> 2) & 127;
        int ch = w & 3;
        src[i] = pT[tile] + (long)row * K + ch * 4;
        dst[i] = tile * TILE_BYTES + row * (SROW * 4) + ch * 16;
    }

    const int nKB = K >> 4;             // BK = 16

    // preload stage 0
#pragma unroll
    for (int i = 0; i < 8; i++) cp16(sb + dst[i], src[i]);
    cp_commit();

    float acc[4][4][4];
#pragma unroll
    for (int mf = 0; mf < 4; mf++)
#pragma unroll
        for (int nf = 0; nf < 4; nf++)
#pragma unroll
            for (int r = 0; r < 4; r++) acc[mf][nf][r] = 0.f;

    for (int kb = 0; kb < nKB; kb++) {
        if (kb + 1 < nKB) {
            uint32_t so = ((kb + 1) & 1) * STAGE_BYTES;
            const long ko = (long)(kb + 1) * 16;
#pragma unroll
            for (int i = 0; i < 8; i++) cp16(sb + so + dst[i], src[i] + ko);
            cp_commit();
            cp_wait<1>();
        } else {
            cp_wait<0>();
        }
        __syncthreads();

        const unsigned* Ah_s = (const unsigned*)(smem + (kb & 1) * STAGE_BYTES);
        const unsigned* Al_s = Ah_s + TILE_BYTES / 4;
        const unsigned* Bh_s = Al_s + TILE_BYTES / 4;
        const unsigned* Bl_s = Bh_s + TILE_BYTES / 4;

#pragma unroll
        for (int ks = 0; ks < 2; ks++) {
            const int k0 = ks * 8;
            // load all B frags (hi+lo) for this k-step
            unsigned bh[4][2], bl[4][2];
#pragma unroll
            for (int nf = 0; nf < 4; nf++) {
                int bidx = (wn * 32 + nf * 8 + grp) * SROW + k0 + qd;
                bh[nf][0] = Bh_s[bidx]; bh[nf][1] = Bh_s[bidx + 4];
                bl[nf][0] = Bl_s[bidx]; bl[nf][1] = Bl_s[bidx + 4];
            }
#pragma unroll
            for (int mf = 0; mf < 4; mf++) {
                int aidx = (wm * 64 + mf * 16 + grp) * SROW + k0 + qd;
                unsigned ah0 = Ah_s[aidx], ah1 = Ah_s[aidx + 8 * SROW];
                unsigned ah2 = Ah_s[aidx + 4], ah3 = Ah_s[aidx + 8 * SROW + 4];
                unsigned al0 = Al_s[aidx], al1 = Al_s[aidx + 8 * SROW];
                unsigned al2 = Al_s[aidx + 4], al3 = Al_s[aidx + 8 * SROW + 4];
#pragma unroll
                for (int nf = 0; nf < 4; nf++) {
                    float* d = acc[mf][nf];
                    mma8(d[0], d[1], d[2], d[3], ah0, ah1, ah2, ah3, bh[nf][0], bh[nf][1]);
                    mma8(d[0], d[1], d[2], d[3], ah0, ah1, ah2, ah3, bl[nf][0], bl[nf][1]);
                    mma8(d[0], d[1], d[2], d[3], al0, al1, al2, al3, bh[nf][0], bh[nf][1]);
                }
            }
        }
        __syncthreads();
    }

    // ---------------- epilogue ----------------
    if constexpr (EPI == 4) {
        unsigned long long* red = (unsigned long long*)(smem + RED_OFF);
        if (tid < 128) red[tid] = 0ull;
        __syncthreads();
#pragma unroll
        for (int mf = 0; mf < 4; mf++) {
#pragma unroll
            for (int half = 0; half < 2; half++) {
                int lrow = wm * 64 + mf * 16 + grp + half * 8;
                float bv = -INFINITY; int bc = 0;
#pragma unroll
                for (int nf = 0; nf < 4; nf++) {
#pragma unroll
                    for (int c = 0; c < 2; c++) {
                        float vv = acc[mf][nf][half * 2 + c];
                        int col = (int)n0 + wn * 32 + nf * 8 + qd * 2 + c;
                        if (vv > bv) { bv = vv; bc = col; }
                    }
                }
                unsigned long long pack =
                    ((unsigned long long)fkey(bv * scale) << 32) | (unsigned int)bc;
                // reduce across the 4 lanes that share this row (qd = 0..3)
                unsigned long long o;
                o = __shfl_xor_sync(0xffffffffu, pack, 1); if (o > pack) pack = o;
                o = __shfl_xor_sync(0xffffffffu, pack, 2); if (o > pack) pack = o;
                if (qd == 0) atomicMax(&red[lrow], pack);
            }
        }
        __syncthreads();
        if (tid < 128)
            atomicMax(&colmax[z * sMz + m0 + tid], red[tid]);
    } else {
#pragma unroll
        for (int mf = 0; mf < 4; mf++) {
#pragma unroll
            for (int half = 0; half < 2; half++) {
                long row = m0 + wm * 64 + mf * 16 + grp + half * 8;
                float rb = 0.f;
                if constexpr (EPI == 3) rb = bias[row];
                long base = z * sCz + row * (long)Nd + n0 + wn * 32 + qd * 2;
#pragma unroll
                for (int nf = 0; nf < 4; nf++) {
                    float v0 = acc[mf][nf][half * 2 + 0];
                    float v1 = acc[mf][nf][half * 2 + 1];
                    long off = base + nf * 8;
                    if constexpr (EPI == 0 || EPI == 1) {
                        if constexpr (EPI == 1) {
                            v0 += bias[n0 + wn * 32 + nf * 8 + qd * 2 + 0];
                            v1 += bias[n0 + wn * 32 + nf * 8 + qd * 2 + 1];
                        }
                        *reinterpret_cast<float2*>(&C0[off]) = make_float2(v0, v1);
                    } else {
                        v0 += rb; v1 += rb;
                        float h0 = tf32_round(v0), l0 = v0 - h0;
                        float h1 = tf32_round(v1), l1 = v1 - h1;
                        *reinterpret_cast<float2*>(&C0[off]) = make_float2(h0, h1);
                        *reinterpret_cast<float2*>(&C1[off]) = make_float2(l0, l1);
                    }
                }
            }
        }
    }
}

// ============================ small kernels ============================
__global__ void init_kernel() {
    int i = blockIdx.x * blockDim.x + threadIdx.x;
    int stride = gridDim.x * blockDim.x;
    for (int j = i; j < BB * TT; j += stride) g_colmax[j] = 0ull;
    for (int j = i; j < BB * NNODE; j += stride) { g_Mkey[j] = 0u; g_Z[j] = 0.f; }
    for (int j = i; j < BB * NNODE * CC; j += stride) g_op[j] = 0.f;
}

__global__ void split2(const float* __restrict__ in, float* __restrict__ hi,
                       float* __restrict__ lo, long n) {
    long i = (long)blockIdx.x * blockDim.x + threadIdx.x;
    long stride = (long)gridDim.x * blockDim.x;
    for (long j = i; j < n; j += stride) {
        float v = in[j];
        float h = tf32_round(v);
        hi[j] = h; lo[j] = v - h;
    }
}

__global__ void transpose_split(const float* __restrict__ x) {
    __shared__ float tile[32][33];
    int z = blockIdx.z;
    int t0 = blockIdx.x * 32, c0 = blockIdx.y * 32;
    int tx = threadIdx.x, ty = threadIdx.y;
#pragma unroll
    for (int i = 0; i < 32; i += 8)
        tile[ty + i][tx] = x[((long)z * TT + t0 + ty + i) * CC + c0 + tx];
    __syncthreads();
#pragma unroll
    for (int i = 0; i < 32; i += 8) {
        float v = tile[tx][ty + i];
        long o = ((long)z * CC + c0 + ty + i) * TT + t0 + tx;
        float h = tf32_round(v);
        g_xTh[o] = h; g_xTl[o] = v - h;
    }
}

__global__ void node_max_kernel() {
    int i = blockIdx.x * blockDim.x + threadIdx.x;
    if (i >= BB * TT) return;
    int b = i / TT;
    unsigned long long p = g_colmax[i];
    unsigned int n = (unsigned int)(p & 0xffffffffu);
    atomicMax(&g_Mkey[b * NNODE + n], (unsigned int)(p >> 32));
}

__global__ void node_sum_kernel() {
    int i = blockIdx.x * blockDim.x + threadIdx.x;
    if (i >= BB * TT) return;
    int b = i / TT;
    unsigned long long p = g_colmax[i];
    unsigned int n = (unsigned int)(p & 0xffffffffu);
    int bn = b * NNODE + n;
    float m = funkey((unsigned int)(p >> 32));
    atomicAdd(&g_Z[bn], expf(m - funkey(g_Mkey[bn])));
}

__global__ void att_scatter_kernel(float* __restrict__ att) {
    int i = blockIdx.x * blockDim.x + threadIdx.x;
    if (i >= BB * TT) return;
    int b = i / TT;
    int t = i % TT;
    unsigned long long p = g_colmax[i];
    unsigned int n = (unsigned int)(p & 0xffffffffu);
    int bn = b * NNODE + n;
    float m = funkey((unsigned int)(p >> 32));
    float w = expf(m - funkey(g_Mkey[bn])) / g_Z[bn];
    att[(long)bn * TT + t] = w;
}

__global__ void outpre_scatter_kernel() {
    int i = blockIdx.x;
    int b = i / TT;
    unsigned long long p = g_colmax[i];
    unsigned int n = (unsigned int)(p & 0xffffffffu);
    int bn = b * NNODE + n;
    float m = funkey((unsigned int)(p >> 32));
    float w = expf(m - funkey(g_Mkey[bn])) / g_Z[bn];
    const float* vrow = g_v + (long)i * CC;
    float* orow = g_op + (long)bn * CC;
    for (int c = threadIdx.x; c < CC; c += blockDim.x)
        atomicAdd(&orow[c], w * vrow[c]);
}

// ============================ launch ============================
extern "C" void kernel_launch(void* const* d_in, const int* in_sizes, int n_in,
                              void* d_out, int out_size)
{
    const float* x    = (const float*)d_in[0];
    const float* Wq   = (const float*)d_in[1];
    const float* bq   = (const float*)d_in[2];
    const float* Wk   = (const float*)d_in[3];
    const float* Wv   = (const float*)d_in[4];
    const float* Wout = (const float*)d_in[5];
    const float* bout = (const float*)d_in[6];

    float* out = (float*)d_out;
    float* att = out + (long)BB * NNODE * CC;

    float *xh, *xl, *xTh, *xTl, *Wqh, *Wql, *Wkh, *Wkl, *Wvh, *Wvl, *Woh, *Wol;
    float *kh, *kl, *vp, *qh, *ql, *op, *oph, *opl;
    unsigned long long* cm;
    cudaGetSymbolAddress((void**)&xh, g_xh);   cudaGetSymbolAddress((void**)&xl, g_xl);
    cudaGetSymbolAddress((void**)&xTh, g_xTh); cudaGetSymbolAddress((void**)&xTl, g_xTl);
    cudaGetSymbolAddress((void**)&Wqh, g_Wqh); cudaGetSymbolAddress((void**)&Wql, g_Wql);
    cudaGetSymbolAddress((void**)&Wkh, g_Wkh); cudaGetSymbolAddress((void**)&Wkl, g_Wkl);
    cudaGetSymbolAddress((void**)&Wvh, g_Wvh); cudaGetSymbolAddress((void**)&Wvl, g_Wvl);
    cudaGetSymbolAddress((void**)&Woh, g_Woh); cudaGetSymbolAddress((void**)&Wol, g_Wol);
    cudaGetSymbolAddress((void**)&kh, g_kh);   cudaGetSymbolAddress((void**)&kl, g_kl);
    cudaGetSymbolAddress((void**)&vp, g_v);
    cudaGetSymbolAddress((void**)&qh, g_qh);   cudaGetSymbolAddress((void**)&ql, g_ql);
    cudaGetSymbolAddress((void**)&op, g_op);
    cudaGetSymbolAddress((void**)&oph, g_oph); cudaGetSymbolAddress((void**)&opl, g_opl);
    cudaGetSymbolAddress((void**)&cm, g_colmax);

    cudaFuncSetAttribute(gemm_mma<0>, cudaFuncAttributeMaxDynamicSharedMemorySize, SMEM_SZ);
    cudaFuncSetAttribute(gemm_mma<1>, cudaFuncAttributeMaxDynamicSharedMemorySize, SMEM_SZ);
    cudaFuncSetAttribute(gemm_mma<2>, cudaFuncAttributeMaxDynamicSharedMemorySize, SMEM_SZ);
    cudaFuncSetAttribute(gemm_mma<3>, cudaFuncAttributeMaxDynamicSharedMemorySize, SMEM_SZ);
    cudaFuncSetAttribute(gemm_mma<4>, cudaFuncAttributeMaxDynamicSharedMemorySize, SMEM_SZ);

    const float scale = 1.0f / sqrtf((float)CC);

    init_kernel<<<2048, 256>>>();
    cudaMemsetAsync(att, 0, (size_t)BB * NNODE * TT * sizeof(float), 0);

    // splits
    split2<<<4096, 256>>>(x, xh, xl, (long)BB * TT * CC);
    transpose_split<<<dim3(TT / 32, CC / 32, BB), dim3(32, 8)>>>(x);
    split2<<<2048, 256>>>(Wq, Wqh, Wql, (long)NNODE * TT);
    split2<<<512, 256>>>(Wk, Wkh, Wkl, (long)CC * CC);
    split2<<<512, 256>>>(Wv, Wvh, Wvl, (long)CC * CC);
    split2<<<512, 256>>>(Wout, Woh, Wol, (long)CC * CC);

    // k = x @ Wk^T -> hi/lo   (M=16384, N=512, K=512)
    gemm_mma<2><<<dim3(4, 128, 1), 256, SMEM_SZ>>>(
        xh, xl, Wkh, Wkl, nullptr, kh, kl, CC, CC, 0, 0, 0, 0.f, nullptr, 0);
    // v = x @ Wv^T -> plain
    gemm_mma<0><<<dim3(4, 128, 1), 256, SMEM_SZ>>>(
        xh, xl, Wvh, Wvl, nullptr, vp, nullptr, CC, CC, 0, 0, 0, 0.f, nullptr, 0);
    // q[b] = Wq @ xT[b]^T + bq -> hi/lo   (M=1024, N=512, K=2048, z=B)
    gemm_mma<3><<<dim3(4, 8, BB), 256, SMEM_SZ>>>(
        Wqh, Wql, xTh, xTl, bq, qh, ql, CC, TT,
        0, (long)CC * TT, (long)NNODE * CC, 0.f, nullptr, 0);
    // sim[b] = scale * k[b] @ q[b]^T, token-major rows, argmax epilogue
    gemm_mma<4><<<dim3(NNODE / 128, TT / 128, BB), 256, SMEM_SZ>>>(
        kh, kl, qh, ql, nullptr, nullptr, nullptr, NNODE, CC,
        (long)TT * CC, (long)NNODE * CC, 0, scale, cm, (long)TT);

    node_max_kernel<<<(BB * TT) / 256, 256>>>();
    node_sum_kernel<<<(BB * TT) / 256, 256>>>();
    att_scatter_kernel<<<(BB * TT) / 256, 256>>>(att);
    outpre_scatter_kernel<<<BB * TT, 128>>>();

    split2<<<2048, 256>>>(op, oph, opl, (long)BB * NNODE * CC);
    // out = outpre @ Wout^T + bout   (M=8192, N=512, K=512)
    gemm_mma<1><<<dim3(4, 64, 1), 256, SMEM_SZ>>>(
        oph, opl, Woh, Wol, bout, out, nullptr, CC, CC, 0, 0, 0, 0.f, nullptr, 0);
}